// round 13
// baseline (speedup 1.0000x reference)
#include <cuda_runtime.h>
#include <cuda_fp16.h>
#include <cstdint>

// ---------------------------------------------------------------------------
// Problem constants
// ---------------------------------------------------------------------------
#define M_DIM 4096      // out features
#define K_DIM 4096      // in features
#define N_DIM 8192      // cols of x / out
#define BM 128          // CTA tile M
#define BN 256          // CTA tile N
#define BK 64           // logical K per stage (stored: 32 halves/row, 2:4)
#define ITERS (K_DIM / BK)   // 64
#define STAGES 4
#define THREADS 256     // 8 warps, 2(m) x 4(n), warp tile 64x64

// smem rows: A stored 32 halves = 64B + 16B pad = 80B; B 64 halves = 128B + 16B = 144B
#define AROW 80
#define BROW 144
#define A_STAGE_B (BM * AROW)             // 10240
#define B_STAGE_B (BN * BROW)             // 36864
#define STAGE_B (A_STAGE_B + B_STAGE_B)   // 47104
#define SMEM_TOTAL (STAGES * STAGE_B)     // 188416

#define FIX_CAP 65536

// ---------------------------------------------------------------------------
// Device scratch.
// ---------------------------------------------------------------------------
__device__ unsigned short g_Wh[(size_t)M_DIM * K_DIM];        // 32 MB dense fp16 panels
__device__ unsigned short g_Wsp[(size_t)M_DIM * K_DIM / 2];   // 16 MB 2:4 stored values
__device__ uint32_t       g_Wmeta[(size_t)M_DIM * (K_DIM / 64) * 2];  // 2 MB metadata
__device__ unsigned short g_Xh[(size_t)N_DIM * K_DIM];        // 64 MB packed xT
__device__ int   g_fix_cnt;
__device__ int   g_fix_m[FIX_CAP];
__device__ int   g_fix_k[FIX_CAP];
__device__ float g_fix_v[FIX_CAP];

// ---------------------------------------------------------------------------
// PTX helpers (sm_80-base ISA)
// ---------------------------------------------------------------------------
__device__ __forceinline__ uint32_t smem_u32(const void* p) {
    uint32_t a;
    asm("{ .reg .u64 t; cvta.to.shared.u64 t, %1; cvt.u32.u64 %0, t; }" : "=r"(a) : "l"(p));
    return a;
}

__device__ __forceinline__ void cp16(uint32_t dst, const void* src) {
    asm volatile("cp.async.cg.shared.global [%0], [%1], 16;" :: "r"(dst), "l"(src));
}

#define CP_COMMIT() asm volatile("cp.async.commit_group;" ::: "memory")
#define CP_WAIT2()  asm volatile("cp.async.wait_group 2;" ::: "memory")

__device__ __forceinline__ void ldsm4(uint32_t r[4], uint32_t addr) {
    asm volatile("ldmatrix.sync.aligned.m8n8.x4.shared.b16 {%0,%1,%2,%3}, [%4];"
        : "=r"(r[0]), "=r"(r[1]), "=r"(r[2]), "=r"(r[3]) : "r"(addr));
}

// Sparse MMA: D(16x8,f32) += A(16x32, 2:4 sparse, stored 16x16) * B(32x8)
// Metadata (corrected, k-split across thread pair): with selector 0x0, in each
// quad T0 carries k0-15 and T1 carries k16-31; each carries BOTH rows:
// bits[0:16] = row (lane>>2), bits[16:32] = row (lane>>2)+8.
__device__ __forceinline__ void mmasp(float d[4], const uint32_t a[4],
                                      uint32_t b0, uint32_t b1, uint32_t b2, uint32_t b3,
                                      uint32_t e) {
    asm volatile(
        "mma.sp::ordered_metadata.sync.aligned.m16n8k32.row.col.f32.f16.f16.f32 "
        "{%0,%1,%2,%3}, {%4,%5,%6,%7}, {%8,%9,%10,%11}, {%0,%1,%2,%3}, %12, 0x0;"
        : "+f"(d[0]), "+f"(d[1]), "+f"(d[2]), "+f"(d[3])
        : "r"(a[0]), "r"(a[1]), "r"(a[2]), "r"(a[3]),
          "r"(b0), "r"(b1), "r"(b2), "r"(b3), "r"(e));
}

// ---------------------------------------------------------------------------
// Preprocessing
// ---------------------------------------------------------------------------
__global__ void clearW_kernel() {
    if (blockIdx.x == 0 && threadIdx.x == 0) g_fix_cnt = 0;
    uint4* p4 = reinterpret_cast<uint4*>(g_Wh) + (size_t)blockIdx.x * 4096;
    uint4 z = make_uint4(0, 0, 0, 0);
#pragma unroll
    for (int i = 0; i < 16; ++i)
        p4[threadIdx.x + i * 256] = z;
}

__global__ void scatter_kernel(const int* __restrict__ rows, const int* __restrict__ cols,
                               const float* __restrict__ vals, int nnz) {
    int i = blockIdx.x * blockDim.x + threadIdx.x;
    if (i < nnz) {
        int m = rows[i], k = cols[i];
        size_t idx = ((size_t)(k >> 6) * M_DIM + m) * 64 + (k & 63);
        atomicAdd(reinterpret_cast<__half*>(g_Wh) + idx, __float2half_rn(vals[i]));
    }
}

// Compress dense fp16 W panels -> 2:4 stored values + metadata + overflow COO.
// Word layout per (row, k64-tile): word w covers groups 8w..8w+7 (k 32w..32w+31),
// group g at bits (g&7)*4, low 2 bits = first (smaller) kept index.
__global__ void compress_kernel() {
    int t = blockIdx.x * 256 + threadIdx.x;           // 262144 total
    int kt = t >> 12;                                  // / 4096
    int m = t & 4095;
    const uint32_t* src = reinterpret_cast<const uint32_t*>(
        g_Wh + ((size_t)kt * M_DIM + m) * 64);
    uint32_t w[32];
#pragma unroll
    for (int j = 0; j < 8; ++j) {
        uint4 v = reinterpret_cast<const uint4*>(src)[j];
        w[4 * j] = v.x; w[4 * j + 1] = v.y; w[4 * j + 2] = v.z; w[4 * j + 3] = v.w;
    }
    unsigned short stored[32];
    uint32_t meta[2] = {0, 0};
#pragma unroll
    for (int g = 0; g < 16; ++g) {
        unsigned short e[4];
#pragma unroll
        for (int j = 0; j < 4; ++j) {
            int idx = 4 * g + j;
            uint32_t word = w[idx >> 1];
            e[j] = (idx & 1) ? (unsigned short)(word >> 16) : (unsigned short)(word & 0xFFFF);
        }
        int i0 = -1, i1 = -1, cnt = 0;
#pragma unroll
        for (int j = 0; j < 4; ++j) {
            if ((e[j] & 0x7FFF) != 0) {
                if (cnt == 0) i0 = j;
                else if (cnt == 1) i1 = j;
                else {
                    int slot = atomicAdd(&g_fix_cnt, 1);
                    if (slot < FIX_CAP) {
                        g_fix_m[slot] = m;
                        g_fix_k[slot] = kt * 64 + 4 * g + j;
                        g_fix_v[slot] = __half2float(*reinterpret_cast<__half*>(&e[j]));
                    }
                }
                cnt++;
            }
        }
        if (cnt == 0) { i0 = 0; i1 = 1; }
        else if (cnt == 1) { if (i0 == 0) i1 = 1; else { i1 = i0; i0 = 0; } }
        stored[2 * g]     = e[i0];
        stored[2 * g + 1] = e[i1];
        meta[g >> 3] |= (uint32_t)((i0 & 3) | ((i1 & 3) << 2)) << ((g & 7) * 4);
    }
    uint4* dstv = reinterpret_cast<uint4*>(g_Wsp + ((size_t)kt * M_DIM + m) * 32);
#pragma unroll
    for (int j = 0; j < 4; ++j)
        dstv[j] = reinterpret_cast<const uint4*>(stored)[j];
    reinterpret_cast<uint2*>(g_Wmeta)[(size_t)kt * M_DIM + m] = make_uint2(meta[0], meta[1]);
}

// Transpose x[K,N] -> packed xT fp16 panels.
__global__ void packX_kernel(const float* __restrict__ x) {
    __shared__ float sh[64][65];
    const int k0 = blockIdx.x * 64;
    const int n0 = blockIdx.y * 64;
    const int t = threadIdx.x;
    const float4* xv = reinterpret_cast<const float4*>(x + (size_t)k0 * N_DIM + n0);
#pragma unroll
    for (int i = 0; i < 4; ++i) {
        int idx = i * 256 + t;
        int kk = idx >> 4, c4 = idx & 15;
        float4 v = xv[(size_t)kk * (N_DIM / 4) + c4];
        sh[kk][c4 * 4 + 0] = v.x;
        sh[kk][c4 * 4 + 1] = v.y;
        sh[kk][c4 * 4 + 2] = v.z;
        sh[kk][c4 * 4 + 3] = v.w;
    }
    __syncthreads();
#pragma unroll
    for (int j = 0; j < 2; ++j) {
        int idx = j * 256 + t;
        int nl = idx >> 3, oct = idx & 7;
        uint4 v;
        uint32_t* vp = &v.x;
#pragma unroll
        for (int q = 0; q < 4; ++q) {
            __half2 h2 = __floats2half2_rn(sh[oct * 8 + 2 * q][nl],
                                           sh[oct * 8 + 2 * q + 1][nl]);
            vp[q] = *reinterpret_cast<uint32_t*>(&h2);
        }
        size_t dst = ((size_t)blockIdx.x * N_DIM + n0 + nl) * 64 + oct * 8;
        *reinterpret_cast<uint4*>(&g_Xh[dst]) = v;
    }
}

// Fixup: out[m, :] += v * x[k, :] for each overflow entry. Runs AFTER gemm.
__global__ void fixup_kernel(const float* __restrict__ x, float* __restrict__ out) {
    int cnt = g_fix_cnt;
    if (cnt > FIX_CAP) cnt = FIX_CAP;
    for (int e = blockIdx.x; e < cnt; e += gridDim.x) {
        int m = g_fix_m[e], k = g_fix_k[e];
        float v = g_fix_v[e];
        const float4* xr = reinterpret_cast<const float4*>(x + (size_t)k * N_DIM);
        float* orow = out + (size_t)m * N_DIM;
#pragma unroll
        for (int j = 0; j < 8; ++j) {
            int c4 = threadIdx.x + j * 256;
            float4 xv = xr[c4];
            atomicAdd(orow + 4 * c4 + 0, v * xv.x);
            atomicAdd(orow + 4 * c4 + 1, v * xv.y);
            atomicAdd(orow + 4 * c4 + 2, v * xv.z);
            atomicAdd(orow + 4 * c4 + 3, v * xv.w);
        }
    }
}

// ---------------------------------------------------------------------------
// Sparse GEMM: out = W(2:4 fp16) * x(fp16), fp32 accumulate. K = 4096.
// CTA 128x256x64(logical), 8 warps (2m x 4n), warp tile 64x64, 4-stage
// cp.async, R5-style rotation with 2 macro-steps (k32 each) per stage.
// ---------------------------------------------------------------------------
__global__ void __launch_bounds__(THREADS, 1) gemm_kernel(float* __restrict__ out) {
    extern __shared__ __align__(128) char smem[];
    const uint32_t sb = smem_u32(smem);
    const int tid = threadIdx.x;
    const int lane = tid & 31;
    const int wid = tid >> 5;
    const int wm = (wid & 1) * 64;
    const int wn = (wid >> 1) * 64;
    const int m0 = blockIdx.x * BM;
    const int n0 = blockIdx.y * BN;

    float acc[4][8][4];
#pragma unroll
    for (int i = 0; i < 4; ++i)
#pragma unroll
        for (int j = 0; j < 8; ++j)
#pragma unroll
            for (int r = 0; r < 4; ++r) acc[i][j][r] = 0.f;

    const uint32_t a_lane_off =
        (uint32_t)((wm + (lane & 15)) * AROW + (lane >> 4) * 16);
    const uint32_t b_lane_off =
        (uint32_t)((wn + (lane & 7) + ((lane >> 4) & 1) * 8) * BROW +
                   ((lane >> 3) & 1) * 16);

    auto load_stage = [&](int kt, int s) {
        const char* asrc = (const char*)g_Wsp + ((size_t)kt * M_DIM + m0) * 64;
        const char* bsrc = (const char*)g_Xh + ((size_t)kt * N_DIM + n0) * 128;
        uint32_t As = sb + s * STAGE_B;
        uint32_t Bs = As + A_STAGE_B;
#pragma unroll
        for (int j = 0; j < 2; ++j) {   // A stored: 512 x 16B chunks (4 per 64B row)
            int c = tid + j * THREADS;
            cp16(As + (uint32_t)((c >> 2) * AROW + (c & 3) * 16), asrc + (size_t)c * 16);
        }
#pragma unroll
        for (int j = 0; j < 8; ++j) {   // B: 2048 x 16B chunks (8 per 128B row)
            int c = tid + j * THREADS;
            cp16(Bs + (uint32_t)((c >> 3) * BROW + (c & 7) * 16), bsrc + (size_t)c * 16);
        }
    };

    // CORRECTED metadata gather (k-split across thread pair):
    //   half = (lane&1): 0 -> k0-15 of the k32 window, 1 -> k16-31.
    //   e bits[0:16]  = row q    = wm + 16*mi + (lane>>2)
    //   e bits[16:32] = row q+8
    // Replicated across lane&2 (selector 0x0 reads T0/T1 only).
    auto ldg_meta = [&](int kt, uint32_t mt[8]) {
        const int half = (lane & 1) * 16;
#pragma unroll
        for (int mi = 0; mi < 4; ++mi) {
            int rq = m0 + wm + mi * 16 + (lane >> 2);
            uint2 mq  = reinterpret_cast<const uint2*>(g_Wmeta)[(size_t)kt * M_DIM + rq];
            uint2 mq8 = reinterpret_cast<const uint2*>(g_Wmeta)[(size_t)kt * M_DIM + rq + 8];
            mt[2 * mi + 0] = ((mq.x  >> half) & 0xFFFFu) |
                             (((mq8.x >> half) & 0xFFFFu) << 16);
            mt[2 * mi + 1] = ((mq.y  >> half) & 0xFFFFu) |
                             (((mq8.y >> half) & 0xFFFFu) << 16);
        }
    };

    auto ldsm_sp = [&](int s, int kstep, uint32_t a[4][4], uint32_t b[2][4][4]) {
        const uint32_t As = sb + s * STAGE_B + a_lane_off + kstep * 32;
        const uint32_t Bs = sb + s * STAGE_B + A_STAGE_B + b_lane_off + kstep * 64;
#pragma unroll
        for (int mi = 0; mi < 4; ++mi) ldsm4(a[mi], As + mi * (16 * AROW));
#pragma unroll
        for (int h = 0; h < 2; ++h)
#pragma unroll
            for (int nj = 0; nj < 4; ++nj)
                ldsm4(b[h][nj], Bs + h * 32 + nj * (16 * BROW));
    };

    auto mma_macro = [&](uint32_t a[4][4], uint32_t b[2][4][4],
                         const uint32_t mt[8], int kstep) {
#pragma unroll
        for (int mi = 0; mi < 4; ++mi) {
            uint32_t e = mt[2 * mi + kstep];
#pragma unroll
            for (int nj = 0; nj < 4; ++nj) {
                mmasp(acc[mi][2 * nj], a[mi],
                      b[0][nj][0], b[0][nj][1], b[1][nj][0], b[1][nj][1], e);
                mmasp(acc[mi][2 * nj + 1], a[mi],
                      b[0][nj][2], b[0][nj][3], b[1][nj][2], b[1][nj][3], e);
            }
        }
    };

    // prologue
#pragma unroll
    for (int s = 0; s < STAGES - 1; ++s) {
        load_stage(s, s);
        CP_COMMIT();
    }
    uint32_t metaCur[8], metaNext[8];
    ldg_meta(0, metaCur);
    uint32_t a0[4][4], b0[2][4][4], a1[4][4], b1[2][4][4];
    CP_WAIT2();
    __syncthreads();
    ldsm_sp(0, 0, a0, b0);

    for (int it = 0; it < ITERS; ++it) {
        const int s = it & (STAGES - 1);
        if (it + 3 < ITERS) load_stage(it + 3, (it + 3) & (STAGES - 1));
        CP_COMMIT();
        if (it + 1 < ITERS) ldg_meta(it + 1, metaNext);

        // macro-step 0 (k 0..31)
        ldsm_sp(s, 1, a1, b1);
        mma_macro(a0, b0, metaCur, 0);
        CP_WAIT2();
        __syncthreads();
        // macro-step 1 (k 32..63)
        if (it + 1 < ITERS) ldsm_sp((it + 1) & (STAGES - 1), 0, a0, b0);
        mma_macro(a1, b1, metaCur, 1);
#pragma unroll
        for (int q = 0; q < 8; ++q) metaCur[q] = metaNext[q];
    }

    // epilogue: direct fp32 stores (overwrite; fixup atomicAdds after)
#pragma unroll
    for (int mi = 0; mi < 4; ++mi) {
        int row = m0 + wm + mi * 16 + (lane >> 2);
#pragma unroll
        for (int ni = 0; ni < 8; ++ni) {
            int col = n0 + wn + ni * 8 + (lane & 3) * 2;
            float2* p0 = reinterpret_cast<float2*>(out + (size_t)row * N_DIM + col);
            float2* p1 = reinterpret_cast<float2*>(out + (size_t)(row + 8) * N_DIM + col);
            *p0 = make_float2(acc[mi][ni][0], acc[mi][ni][1]);
            *p1 = make_float2(acc[mi][ni][2], acc[mi][ni][3]);
        }
    }
}

// ---------------------------------------------------------------------------
// Launch: clearW -> scatter -> compress -> packX -> gemm -> fixup
// ---------------------------------------------------------------------------
extern "C" void kernel_launch(void* const* d_in, const int* in_sizes, int n_in,
                              void* d_out, int out_size) {
    const int*   rows = (const int*)d_in[0];
    const int*   cols = (const int*)d_in[1];
    const float* vals = (const float*)d_in[2];
    const float* x    = (const float*)d_in[3];
    float* out = (float*)d_out;
    int nnz = in_sizes[0];

    static int smem_set = 0;
    if (!smem_set) {
        cudaFuncSetAttribute(gemm_kernel, cudaFuncAttributeMaxDynamicSharedMemorySize,
                             SMEM_TOTAL);
        smem_set = 1;
    }

    clearW_kernel<<<512, 256>>>();
    scatter_kernel<<<(nnz + 255) / 256, 256>>>(rows, cols, vals, nnz);
    compress_kernel<<<1024, 256>>>();
    packX_kernel<<<dim3(K_DIM / 64, N_DIM / 64), 256>>>(x);
    gemm_kernel<<<dim3(M_DIM / BM, N_DIM / BN), THREADS, SMEM_TOTAL>>>(out);
    fixup_kernel<<<1024, 256>>>(x, out);
}

// round 14
// speedup vs baseline: 1.2913x; 1.2913x over previous
#include <cuda_runtime.h>
#include <cuda_fp16.h>
#include <cstdint>

// ---------------------------------------------------------------------------
// Problem constants
// ---------------------------------------------------------------------------
#define M_DIM 4096      // out features
#define K_DIM 4096      // in features
#define N_DIM 8192      // cols of x / out
#define BM 128          // CTA tile M
#define BN 256          // CTA tile N
#define BK 64           // logical K per stage (stored: 32 halves/row, 2:4)
#define ITERS (K_DIM / BK)   // 64
#define STAGES 4
#define THREADS 256     // 8 warps, 2(m) x 4(n), warp tile 64x64

// smem rows: A stored 32 halves = 64B + 16B pad = 80B; B 64 halves = 128B + 16B = 144B
#define AROW 80
#define BROW 144
#define A_STAGE_B (BM * AROW)             // 10240
#define B_STAGE_B (BN * BROW)             // 36864
#define META_OFF (A_STAGE_B + B_STAGE_B)  // 47104
#define META_B 1024
#define STAGE_B (META_OFF + META_B)       // 48128
#define SMEM_TOTAL (STAGES * STAGE_B)     // 192512

#define FIX_CAP 65536

// ---------------------------------------------------------------------------
// Device scratch.
// ---------------------------------------------------------------------------
__device__ unsigned short g_Wh[(size_t)M_DIM * K_DIM];        // 32 MB dense fp16 panels
__device__ unsigned short g_Wsp[(size_t)M_DIM * K_DIM / 2];   // 16 MB 2:4 stored values
__device__ uint32_t       g_Wmeta[(size_t)M_DIM * (K_DIM / 64) * 2];  // 2 MB raw metadata
// Pre-combined per-thread metadata: E[kt][mb][pair][half][w], w=kstep.
//   word = lo16(meta[row=mb*16+pair].word[half-sel w]) | hi16(row+8 same)
__device__ uint32_t       g_WmE[(size_t)64 * 256 * 8 * 2 * 2];        // 2 MB
__device__ unsigned short g_Xh[(size_t)N_DIM * K_DIM];        // 64 MB packed xT
__device__ int   g_fix_cnt;
__device__ int   g_fix_m[FIX_CAP];
__device__ int   g_fix_k[FIX_CAP];
__device__ float g_fix_v[FIX_CAP];

// ---------------------------------------------------------------------------
// PTX helpers (sm_80-base ISA)
// ---------------------------------------------------------------------------
__device__ __forceinline__ uint32_t smem_u32(const void* p) {
    uint32_t a;
    asm("{ .reg .u64 t; cvta.to.shared.u64 t, %1; cvt.u32.u64 %0, t; }" : "=r"(a) : "l"(p));
    return a;
}

__device__ __forceinline__ void cp16(uint32_t dst, const void* src) {
    asm volatile("cp.async.cg.shared.global [%0], [%1], 16;" :: "r"(dst), "l"(src));
}

#define CP_COMMIT() asm volatile("cp.async.commit_group;" ::: "memory")
#define CP_WAIT2()  asm volatile("cp.async.wait_group 2;" ::: "memory")

__device__ __forceinline__ void ldsm4(uint32_t r[4], uint32_t addr) {
    asm volatile("ldmatrix.sync.aligned.m8n8.x4.shared.b16 {%0,%1,%2,%3}, [%4];"
        : "=r"(r[0]), "=r"(r[1]), "=r"(r[2]), "=r"(r[3]) : "r"(addr));
}

// Sparse MMA (metadata layout verified in R12): selector 0x0; in each quad
// T0 carries k0-15, T1 carries k16-31; bits[0:16]=row q, bits[16:32]=row q+8.
__device__ __forceinline__ void mmasp(float d[4], const uint32_t a[4],
                                      uint32_t b0, uint32_t b1, uint32_t b2, uint32_t b3,
                                      uint32_t e) {
    asm volatile(
        "mma.sp::ordered_metadata.sync.aligned.m16n8k32.row.col.f32.f16.f16.f32 "
        "{%0,%1,%2,%3}, {%4,%5,%6,%7}, {%8,%9,%10,%11}, {%0,%1,%2,%3}, %12, 0x0;"
        : "+f"(d[0]), "+f"(d[1]), "+f"(d[2]), "+f"(d[3])
        : "r"(a[0]), "r"(a[1]), "r"(a[2]), "r"(a[3]),
          "r"(b0), "r"(b1), "r"(b2), "r"(b3), "r"(e));
}

// ---------------------------------------------------------------------------
// Preprocessing
// ---------------------------------------------------------------------------
__global__ void clearW_kernel() {
    if (blockIdx.x == 0 && threadIdx.x == 0) g_fix_cnt = 0;
    uint4* p4 = reinterpret_cast<uint4*>(g_Wh) + (size_t)blockIdx.x * 4096;
    uint4 z = make_uint4(0, 0, 0, 0);
#pragma unroll
    for (int i = 0; i < 16; ++i)
        p4[threadIdx.x + i * 256] = z;
}

__global__ void scatter_kernel(const int* __restrict__ rows, const int* __restrict__ cols,
                               const float* __restrict__ vals, int nnz) {
    int i = blockIdx.x * blockDim.x + threadIdx.x;
    if (i < nnz) {
        int m = rows[i], k = cols[i];
        size_t idx = ((size_t)(k >> 6) * M_DIM + m) * 64 + (k & 63);
        atomicAdd(reinterpret_cast<__half*>(g_Wh) + idx, __float2half_rn(vals[i]));
    }
}

// Compress dense fp16 W panels -> 2:4 stored values + metadata + overflow COO.
__global__ void compress_kernel() {
    int t = blockIdx.x * 256 + threadIdx.x;           // 262144 total
    int kt = t >> 12;
    int m = t & 4095;
    const uint32_t* src = reinterpret_cast<const uint32_t*>(
        g_Wh + ((size_t)kt * M_DIM + m) * 64);
    uint32_t w[32];
#pragma unroll
    for (int j = 0; j < 8; ++j) {
        uint4 v = reinterpret_cast<const uint4*>(src)[j];
        w[4 * j] = v.x; w[4 * j + 1] = v.y; w[4 * j + 2] = v.z; w[4 * j + 3] = v.w;
    }
    unsigned short stored[32];
    uint32_t meta[2] = {0, 0};
#pragma unroll
    for (int g = 0; g < 16; ++g) {
        unsigned short e[4];
#pragma unroll
        for (int j = 0; j < 4; ++j) {
            int idx = 4 * g + j;
            uint32_t word = w[idx >> 1];
            e[j] = (idx & 1) ? (unsigned short)(word >> 16) : (unsigned short)(word & 0xFFFF);
        }
        int i0 = -1, i1 = -1, cnt = 0;
#pragma unroll
        for (int j = 0; j < 4; ++j) {
            if ((e[j] & 0x7FFF) != 0) {
                if (cnt == 0) i0 = j;
                else if (cnt == 1) i1 = j;
                else {
                    int slot = atomicAdd(&g_fix_cnt, 1);
                    if (slot < FIX_CAP) {
                        g_fix_m[slot] = m;
                        g_fix_k[slot] = kt * 64 + 4 * g + j;
                        g_fix_v[slot] = __half2float(*reinterpret_cast<__half*>(&e[j]));
                    }
                }
                cnt++;
            }
        }
        if (cnt == 0) { i0 = 0; i1 = 1; }
        else if (cnt == 1) { if (i0 == 0) i1 = 1; else { i1 = i0; i0 = 0; } }
        stored[2 * g]     = e[i0];
        stored[2 * g + 1] = e[i1];
        meta[g >> 3] |= (uint32_t)((i0 & 3) | ((i1 & 3) << 2)) << ((g & 7) * 4);
    }
    uint4* dstv = reinterpret_cast<uint4*>(g_Wsp + ((size_t)kt * M_DIM + m) * 32);
#pragma unroll
    for (int j = 0; j < 4; ++j)
        dstv[j] = reinterpret_cast<const uint4*>(stored)[j];
    reinterpret_cast<uint2*>(g_Wmeta)[(size_t)kt * M_DIM + m] = make_uint2(meta[0], meta[1]);
}

// Pre-combine metadata into the exact per-thread words the mma.sp needs:
//   E[kt][mb][p][h] (uint2, words w=0,1 = kstep) with
//   word = lo16(meta[mb*16+p].w >> 16h) | hi16(meta[mb*16+p+8].w >> 16h)
__global__ void repack_meta_kernel() {
    int t = blockIdx.x * 256 + threadIdx.x;   // 262144 total
    int h = t & 1;
    int p = (t >> 1) & 7;
    int mb = (t >> 4) & 255;
    int kt = t >> 12;
    const uint2* mrow = reinterpret_cast<const uint2*>(g_Wmeta);
    uint2 m1 = mrow[(size_t)kt * M_DIM + mb * 16 + p];
    uint2 m2 = mrow[(size_t)kt * M_DIM + mb * 16 + p + 8];
    int sh = h * 16;
    uint2 e;
    e.x = ((m1.x >> sh) & 0xFFFFu) | (((m2.x >> sh) & 0xFFFFu) << 16);
    e.y = ((m1.y >> sh) & 0xFFFFu) | (((m2.y >> sh) & 0xFFFFu) << 16);
    reinterpret_cast<uint2*>(g_WmE)[((size_t)(kt * 256 + mb) * 8 + p) * 2 + h] = e;
}

// Transpose x[K,N] -> packed xT fp16 panels.
__global__ void packX_kernel(const float* __restrict__ x) {
    __shared__ float sh[64][65];
    const int k0 = blockIdx.x * 64;
    const int n0 = blockIdx.y * 64;
    const int t = threadIdx.x;
    const float4* xv = reinterpret_cast<const float4*>(x + (size_t)k0 * N_DIM + n0);
#pragma unroll
    for (int i = 0; i < 4; ++i) {
        int idx = i * 256 + t;
        int kk = idx >> 4, c4 = idx & 15;
        float4 v = xv[(size_t)kk * (N_DIM / 4) + c4];
        sh[kk][c4 * 4 + 0] = v.x;
        sh[kk][c4 * 4 + 1] = v.y;
        sh[kk][c4 * 4 + 2] = v.z;
        sh[kk][c4 * 4 + 3] = v.w;
    }
    __syncthreads();
#pragma unroll
    for (int j = 0; j < 2; ++j) {
        int idx = j * 256 + t;
        int nl = idx >> 3, oct = idx & 7;
        uint4 v;
        uint32_t* vp = &v.x;
#pragma unroll
        for (int q = 0; q < 4; ++q) {
            __half2 h2 = __floats2half2_rn(sh[oct * 8 + 2 * q][nl],
                                           sh[oct * 8 + 2 * q + 1][nl]);
            vp[q] = *reinterpret_cast<uint32_t*>(&h2);
        }
        size_t dst = ((size_t)blockIdx.x * N_DIM + n0 + nl) * 64 + oct * 8;
        *reinterpret_cast<uint4*>(&g_Xh[dst]) = v;
    }
}

// Fixup: out[m, :] += v * x[k, :] for each overflow entry. Runs AFTER gemm.
__global__ void fixup_kernel(const float* __restrict__ x, float* __restrict__ out) {
    int cnt = g_fix_cnt;
    if (cnt > FIX_CAP) cnt = FIX_CAP;
    for (int e = blockIdx.x; e < cnt; e += gridDim.x) {
        int m = g_fix_m[e], k = g_fix_k[e];
        float v = g_fix_v[e];
        const float4* xr = reinterpret_cast<const float4*>(x + (size_t)k * N_DIM);
        float* orow = out + (size_t)m * N_DIM;
#pragma unroll
        for (int j = 0; j < 8; ++j) {
            int c4 = threadIdx.x + j * 256;
            float4 xv = xr[c4];
            atomicAdd(orow + 4 * c4 + 0, v * xv.x);
            atomicAdd(orow + 4 * c4 + 1, v * xv.y);
            atomicAdd(orow + 4 * c4 + 2, v * xv.z);
            atomicAdd(orow + 4 * c4 + 3, v * xv.w);
        }
    }
}

// ---------------------------------------------------------------------------
// Sparse GEMM: out = W(2:4 fp16) * x(fp16), fp32 accumulate. K = 4096.
// CTA 128x256x64(logical), 8 warps (2m x 4n), warp 64x64, 4-stage cp.async.
// Metadata staged through smem with the operands (1KB/stage) and read
// just-in-time as single LDS.32 per (mi, kstep) — no gmem chains, no extra
// live registers in the hot loop.
// ---------------------------------------------------------------------------
__global__ void __launch_bounds__(THREADS, 1) gemm_kernel(float* __restrict__ out) {
    extern __shared__ __align__(128) char smem[];
    const uint32_t sb = smem_u32(smem);
    const int tid = threadIdx.x;
    const int lane = tid & 31;
    const int wid = tid >> 5;
    const int wm = (wid & 1) * 64;
    const int wn = (wid >> 1) * 64;
    const int m0 = blockIdx.x * BM;
    const int n0 = blockIdx.y * BN;

    float acc[4][8][4];
#pragma unroll
    for (int i = 0; i < 4; ++i)
#pragma unroll
        for (int j = 0; j < 8; ++j)
#pragma unroll
            for (int r = 0; r < 4; ++r) acc[i][j][r] = 0.f;

    const uint32_t a_lane_off =
        (uint32_t)((wm + (lane & 15)) * AROW + (lane >> 4) * 16);
    const uint32_t b_lane_off =
        (uint32_t)((wn + (lane & 7) + ((lane >> 4) & 1) * 8) * BROW +
                   ((lane >> 3) & 1) * 16);
    // smem metadata byte offset: pair*16 + half*8 (mbloc*128 + kstep*4 added per read)
    const uint32_t meta_lane = (uint32_t)((lane >> 2) * 16 + (lane & 1) * 8);
    const uint32_t meta_mbase = (uint32_t)((wm >> 4) * 128) + meta_lane;

    auto load_stage = [&](int kt, int s) {
        const char* asrc = (const char*)g_Wsp + ((size_t)kt * M_DIM + m0) * 64;
        const char* bsrc = (const char*)g_Xh + ((size_t)kt * N_DIM + n0) * 128;
        uint32_t As = sb + s * STAGE_B;
        uint32_t Bs = As + A_STAGE_B;
#pragma unroll
        for (int j = 0; j < 2; ++j) {   // A stored: 512 x 16B chunks (4 per 64B row)
            int c = tid + j * THREADS;
            cp16(As + (uint32_t)((c >> 2) * AROW + (c & 3) * 16), asrc + (size_t)c * 16);
        }
#pragma unroll
        for (int j = 0; j < 8; ++j) {   // B: 2048 x 16B chunks (8 per 128B row)
            int c = tid + j * THREADS;
            cp16(Bs + (uint32_t)((c >> 3) * BROW + (c & 7) * 16), bsrc + (size_t)c * 16);
        }
        if (tid < 64) {                 // metadata: 1KB contiguous
            const char* msrc = (const char*)g_WmE +
                ((size_t)(kt * 256 + (m0 >> 4)) * 32) * 4 + (size_t)tid * 16;
            cp16(As + META_OFF + (uint32_t)tid * 16, msrc);
        }
    };

    auto ldsm_sp = [&](int s, int kstep, uint32_t a[4][4], uint32_t b[2][4][4]) {
        const uint32_t As = sb + s * STAGE_B + a_lane_off + kstep * 32;
        const uint32_t Bs = sb + s * STAGE_B + A_STAGE_B + b_lane_off + kstep * 64;
#pragma unroll
        for (int mi = 0; mi < 4; ++mi) ldsm4(a[mi], As + mi * (16 * AROW));
#pragma unroll
        for (int h = 0; h < 2; ++h)
#pragma unroll
            for (int nj = 0; nj < 4; ++nj)
                ldsm4(b[h][nj], Bs + h * 32 + nj * (16 * BROW));
    };

    auto mma_macro = [&](int s, int kstep, uint32_t a[4][4], uint32_t b[2][4][4]) {
        const uint32_t mbase = sb + s * STAGE_B + META_OFF + meta_mbase + kstep * 4;
#pragma unroll
        for (int mi = 0; mi < 4; ++mi) {
            uint32_t e;
            asm volatile("ld.shared.b32 %0, [%1];" : "=r"(e) : "r"(mbase + mi * 128));
#pragma unroll
            for (int nj = 0; nj < 4; ++nj) {
                mmasp(acc[mi][2 * nj], a[mi],
                      b[0][nj][0], b[0][nj][1], b[1][nj][0], b[1][nj][1], e);
                mmasp(acc[mi][2 * nj + 1], a[mi],
                      b[0][nj][2], b[0][nj][3], b[1][nj][2], b[1][nj][3], e);
            }
        }
    };

    // prologue
#pragma unroll
    for (int s = 0; s < STAGES - 1; ++s) {
        load_stage(s, s);
        CP_COMMIT();
    }
    uint32_t a0[4][4], b0[2][4][4], a1[4][4], b1[2][4][4];
    CP_WAIT2();
    __syncthreads();
    ldsm_sp(0, 0, a0, b0);

    for (int it = 0; it < ITERS; ++it) {
        const int s = it & (STAGES - 1);
        if (it + 3 < ITERS) load_stage(it + 3, (it + 3) & (STAGES - 1));
        CP_COMMIT();

        // macro-step 0 (k 0..31)
        ldsm_sp(s, 1, a1, b1);
        mma_macro(s, 0, a0, b0);
        CP_WAIT2();
        __syncthreads();
        // macro-step 1 (k 32..63)
        if (it + 1 < ITERS) ldsm_sp((it + 1) & (STAGES - 1), 0, a0, b0);
        mma_macro(s, 1, a1, b1);
    }

    // epilogue: direct fp32 stores (overwrite; fixup atomicAdds after)
#pragma unroll
    for (int mi = 0; mi < 4; ++mi) {
        int row = m0 + wm + mi * 16 + (lane >> 2);
#pragma unroll
        for (int ni = 0; ni < 8; ++ni) {
            int col = n0 + wn + ni * 8 + (lane & 3) * 2;
            float2* p0 = reinterpret_cast<float2*>(out + (size_t)row * N_DIM + col);
            float2* p1 = reinterpret_cast<float2*>(out + (size_t)(row + 8) * N_DIM + col);
            *p0 = make_float2(acc[mi][ni][0], acc[mi][ni][1]);
            *p1 = make_float2(acc[mi][ni][2], acc[mi][ni][3]);
        }
    }
}

// ---------------------------------------------------------------------------
// Launch: clearW -> scatter -> compress -> repack -> packX -> gemm -> fixup
// ---------------------------------------------------------------------------
extern "C" void kernel_launch(void* const* d_in, const int* in_sizes, int n_in,
                              void* d_out, int out_size) {
    const int*   rows = (const int*)d_in[0];
    const int*   cols = (const int*)d_in[1];
    const float* vals = (const float*)d_in[2];
    const float* x    = (const float*)d_in[3];
    float* out = (float*)d_out;
    int nnz = in_sizes[0];

    static int smem_set = 0;
    if (!smem_set) {
        cudaFuncSetAttribute(gemm_kernel, cudaFuncAttributeMaxDynamicSharedMemorySize,
                             SMEM_TOTAL);
        smem_set = 1;
    }

    clearW_kernel<<<512, 256>>>();
    scatter_kernel<<<(nnz + 255) / 256, 256>>>(rows, cols, vals, nnz);
    compress_kernel<<<1024, 256>>>();
    repack_meta_kernel<<<1024, 256>>>();
    packX_kernel<<<dim3(K_DIM / 64, N_DIM / 64), 256>>>(x);
    gemm_kernel<<<dim3(M_DIM / BM, N_DIM / BN), THREADS, SMEM_TOTAL>>>(out);
    fixup_kernel<<<1024, 256>>>(x, out);
}

// round 15
// speedup vs baseline: 1.4533x; 1.1255x over previous
#include <cuda_runtime.h>
#include <cuda_fp16.h>
#include <cstdint>

// ---------------------------------------------------------------------------
// Problem constants
// ---------------------------------------------------------------------------
#define M_DIM 4096      // out features
#define K_DIM 4096      // in features
#define N_DIM 8192      // cols of x / out
#define BM 128          // CTA tile M
#define BN 256          // CTA tile N
#define BK 64           // K per stage
#define ITERS (K_DIM / BK)   // 64
#define STAGES 4
#define THREADS 256     // 8 warps, 2(m) x 4(n), warp tile 64x64

// smem rows: 64 halves = 128B data + 16B pad = 144B (conflict-free ldmatrix)
#define ROW_B 144
#define A_STAGE_B (BM * ROW_B)            // 18432
#define B_STAGE_B (BN * ROW_B)            // 36864
#define STAGE_B (A_STAGE_B + B_STAGE_B)   // 55296
#define SMEM_TOTAL (STAGES * STAGE_B)     // 221184

// ---------------------------------------------------------------------------
// Device scratch. Packed k-major 64-wide panels:
//   elem(m, k) -> g_Wh[ ((k>>6)*M_DIM + m)*64 + (k&63) ]
//   elem(n, k) -> g_Xh[ ((k>>6)*N_DIM + n)*64 + (k&63) ]
// ---------------------------------------------------------------------------
__device__ unsigned short g_Wh[(size_t)M_DIM * K_DIM];   // 32 MB fp16
__device__ unsigned short g_Xh[(size_t)N_DIM * K_DIM];   // 64 MB fp16

// ---------------------------------------------------------------------------
// PTX helpers (sm_80-base ISA only)
// ---------------------------------------------------------------------------
__device__ __forceinline__ uint32_t smem_u32(const void* p) {
    uint32_t a;
    asm("{ .reg .u64 t; cvta.to.shared.u64 t, %1; cvt.u32.u64 %0, t; }" : "=r"(a) : "l"(p));
    return a;
}

__device__ __forceinline__ void cp16(uint32_t dst, const void* src) {
    asm volatile("cp.async.cg.shared.global [%0], [%1], 16;" :: "r"(dst), "l"(src));
}

#define CP_COMMIT() asm volatile("cp.async.commit_group;" ::: "memory")
#define CP_WAIT2()  asm volatile("cp.async.wait_group 2;" ::: "memory")

__device__ __forceinline__ void ldsm4(uint32_t r[4], uint32_t addr) {
    asm volatile("ldmatrix.sync.aligned.m8n8.x4.shared.b16 {%0,%1,%2,%3}, [%4];"
        : "=r"(r[0]), "=r"(r[1]), "=r"(r[2]), "=r"(r[3]) : "r"(addr));
}

__device__ __forceinline__ void mma16816(float d[4], const uint32_t a[4],
                                         uint32_t b0, uint32_t b1) {
    asm volatile(
        "mma.sync.aligned.m16n8k16.row.col.f32.f16.f16.f32 "
        "{%0,%1,%2,%3}, {%4,%5,%6,%7}, {%8,%9}, {%0,%1,%2,%3};"
        : "+f"(d[0]), "+f"(d[1]), "+f"(d[2]), "+f"(d[3])
        : "r"(a[0]), "r"(a[1]), "r"(a[2]), "r"(a[3]), "r"(b0), "r"(b1));
}

// ---------------------------------------------------------------------------
// Preprocessing: fused [packX | clearW] kernel (measured 37.1us), then scatter.
// grid = (64, 136): y < 128 -> packX 64x64 tile; y >= 128 -> clear W slice.
// ---------------------------------------------------------------------------
__global__ void prep_kernel(const float* __restrict__ x) {
    if (blockIdx.y < 128) {
        // ---- packX: transpose x[K,N] -> packed xT fp16 panels ----
        __shared__ float sh[64][65];
        const int k0 = blockIdx.x * 64;
        const int n0 = blockIdx.y * 64;
        const int t = threadIdx.x;    // 256 threads

        const float4* xv = reinterpret_cast<const float4*>(x + (size_t)k0 * N_DIM + n0);
#pragma unroll
        for (int i = 0; i < 4; ++i) {
            int idx = i * 256 + t;
            int kk = idx >> 4, c4 = idx & 15;
            float4 v = xv[(size_t)kk * (N_DIM / 4) + c4];
            sh[kk][c4 * 4 + 0] = v.x;
            sh[kk][c4 * 4 + 1] = v.y;
            sh[kk][c4 * 4 + 2] = v.z;
            sh[kk][c4 * 4 + 3] = v.w;
        }
        __syncthreads();
#pragma unroll
        for (int j = 0; j < 2; ++j) {  // 512 uint4 stores (64 n-rows x 8 octets)
            int idx = j * 256 + t;
            int nl = idx >> 3, oct = idx & 7;
            uint4 v;
            uint32_t* vp = &v.x;
#pragma unroll
            for (int q = 0; q < 4; ++q) {
                __half2 h2 = __floats2half2_rn(sh[oct * 8 + 2 * q][nl],
                                               sh[oct * 8 + 2 * q + 1][nl]);
                vp[q] = *reinterpret_cast<uint32_t*>(&h2);
            }
            size_t dst = ((size_t)blockIdx.x * N_DIM + n0 + nl) * 64 + oct * 8;
            *reinterpret_cast<uint4*>(&g_Xh[dst]) = v;
        }
    } else {
        // ---- clearW: 512 slices x 64KB ----
        int slice = blockIdx.x * 8 + (blockIdx.y - 128);   // 0..511
        uint4* p4 = reinterpret_cast<uint4*>(g_Wh) + (size_t)slice * 4096;
        uint4 z = make_uint4(0, 0, 0, 0);
#pragma unroll
        for (int i = 0; i < 16; ++i)
            p4[threadIdx.x + i * 256] = z;
    }
}

// Scatter COO directly into the packed fp16 panel layout with half atomics.
__global__ void scatter_kernel(const int* __restrict__ rows, const int* __restrict__ cols,
                               const float* __restrict__ vals, int nnz) {
    int i = blockIdx.x * blockDim.x + threadIdx.x;
    if (i < nnz) {
        int m = rows[i], k = cols[i];
        size_t idx = ((size_t)(k >> 6) * M_DIM + m) * 64 + (k & 63);
        atomicAdd(reinterpret_cast<__half*>(g_Wh) + idx, __float2half_rn(vals[i]));
    }
}

// ---------------------------------------------------------------------------
// Main GEMM (champion, verbatim): out = W(fp16) * x(fp16), fp32 accum.
// CTA 128x256x64, 8 warps (2m x 4n), warp tile 64x64, 4-stage cp.async.
// CUTLASS-style rotation: wait+sync buried mid-k-loop behind pending MMAs;
// step-0 ldsm of the next stage prefetched at ks=3 so the tensor pipe never
// drains at stage boundaries. Measured: 528-531us, tensor 85.8% — at the
// sm_103a legacy-HMMA rate ceiling (~9.3 cyc/instr/SMSP).
// ---------------------------------------------------------------------------
__global__ void __launch_bounds__(THREADS, 1) gemm_kernel(float* __restrict__ out) {
    extern __shared__ __align__(128) char smem[];
    const uint32_t sb = smem_u32(smem);
    const int tid = threadIdx.x;
    const int lane = tid & 31;
    const int wid = tid >> 5;
    const int wm = (wid & 1) * 64;    // warp m offset
    const int wn = (wid >> 1) * 64;   // warp n offset
    const int m0 = blockIdx.x * BM;
    const int n0 = blockIdx.y * BN;

    float acc[4][8][4];
#pragma unroll
    for (int i = 0; i < 4; ++i)
#pragma unroll
        for (int j = 0; j < 8; ++j)
#pragma unroll
            for (int r = 0; r < 4; ++r) acc[i][j][r] = 0.f;

    const uint32_t a_lane_off =
        (uint32_t)((wm + (lane & 15)) * ROW_B + (lane >> 4) * 16);
    const uint32_t b_lane_off =
        (uint32_t)((wn + (lane & 7) + ((lane >> 4) & 1) * 8) * ROW_B +
                   ((lane >> 3) & 1) * 16);

    auto load_stage = [&](int kt, int s) {
        const char* asrc = (const char*)g_Wh + ((size_t)kt * M_DIM + m0) * 128;
        const char* bsrc = (const char*)g_Xh + ((size_t)kt * N_DIM + n0) * 128;
        uint32_t As = sb + s * STAGE_B;
        uint32_t Bs = As + A_STAGE_B;
#pragma unroll
        for (int j = 0; j < 4; ++j) {   // A: 1024 x 16B chunks (8 per 128B row)
            int c = tid + j * THREADS;
            cp16(As + (uint32_t)((c >> 3) * ROW_B + (c & 7) * 16), asrc + (size_t)c * 16);
        }
#pragma unroll
        for (int j = 0; j < 8; ++j) {   // B: 2048 x 16B chunks
            int c = tid + j * THREADS;
            cp16(Bs + (uint32_t)((c >> 3) * ROW_B + (c & 7) * 16), bsrc + (size_t)c * 16);
        }
    };

    auto ldsm_step = [&](int s, int ks, uint32_t a[4][4], uint32_t b[4][4]) {
        const uint32_t As = sb + s * STAGE_B + a_lane_off + ks * 32;
        const uint32_t Bs = sb + s * STAGE_B + A_STAGE_B + b_lane_off + ks * 32;
#pragma unroll
        for (int mi = 0; mi < 4; ++mi) ldsm4(a[mi], As + mi * (16 * ROW_B));
#pragma unroll
        for (int nj = 0; nj < 4; ++nj) ldsm4(b[nj], Bs + nj * (16 * ROW_B));
    };

    auto mma_step = [&](uint32_t a[4][4], uint32_t b[4][4]) {
#pragma unroll
        for (int mi = 0; mi < 4; ++mi)
#pragma unroll
            for (int nj = 0; nj < 4; ++nj) {
                mma16816(acc[mi][2 * nj], a[mi], b[nj][0], b[nj][1]);
                mma16816(acc[mi][2 * nj + 1], a[mi], b[nj][2], b[nj][3]);
            }
    };

    // prologue: fill 3 of 4 stages, then prime step-0 operands of stage 0
#pragma unroll
    for (int s = 0; s < STAGES - 1; ++s) {
        load_stage(s, s);
        CP_COMMIT();
    }
    uint32_t a[2][4][4], b[2][4][4];
    CP_WAIT2();           // stage 0 complete
    __syncthreads();      // cross-thread visibility
    ldsm_step(0, 0, a[0], b[0]);

    for (int it = 0; it < ITERS; ++it) {
        const int s = it & (STAGES - 1);
        // Issue next gmem loads while tensor pipe drains previous MMAs.
        // Slot (it+3)&3 was last READ before the sync at iter it-1's ks==2.
        if (it + 3 < ITERS) load_stage(it + 3, (it + 3) & (STAGES - 1));
        CP_COMMIT();       // always commit to keep group counting uniform

        // ks = 0
        ldsm_step(s, 1, a[1], b[1]);
        mma_step(a[0], b[0]);
        // ks = 1
        ldsm_step(s, 2, a[0], b[0]);
        mma_step(a[1], b[1]);
        // ks = 2: last read of stage s issued, then wait+sync hidden behind
        //         the 32 pending HMMAs of this mma_step.
        ldsm_step(s, 3, a[1], b[1]);
        mma_step(a[0], b[0]);
        CP_WAIT2();        // guarantees stage it+1 complete (2 newest in flight)
        __syncthreads();   // visibility for stage it+1 + slot reuse protection
        // ks = 3: prefetch step 0 of next stage, then final mma of stage s.
        if (it + 1 < ITERS) ldsm_step((it + 1) & (STAGES - 1), 0, a[0], b[0]);
        mma_step(a[1], b[1]);
    }

    // epilogue: direct fp32 stores
#pragma unroll
    for (int mi = 0; mi < 4; ++mi) {
        int row = m0 + wm + mi * 16 + (lane >> 2);
#pragma unroll
        for (int ni = 0; ni < 8; ++ni) {
            int col = n0 + wn + ni * 8 + (lane & 3) * 2;
            float2* p0 = reinterpret_cast<float2*>(out + (size_t)row * N_DIM + col);
            float2* p1 = reinterpret_cast<float2*>(out + (size_t)(row + 8) * N_DIM + col);
            *p0 = make_float2(acc[mi][ni][0], acc[mi][ni][1]);
            *p1 = make_float2(acc[mi][ni][2], acc[mi][ni][3]);
        }
    }
}

// ---------------------------------------------------------------------------
// Launch
// ---------------------------------------------------------------------------
extern "C" void kernel_launch(void* const* d_in, const int* in_sizes, int n_in,
                              void* d_out, int out_size) {
    const int*   rows = (const int*)d_in[0];
    const int*   cols = (const int*)d_in[1];
    const float* vals = (const float*)d_in[2];
    const float* x    = (const float*)d_in[3];
    float* out = (float*)d_out;
    int nnz = in_sizes[0];

    static int smem_set = 0;
    if (!smem_set) {
        cudaFuncSetAttribute(gemm_kernel, cudaFuncAttributeMaxDynamicSharedMemorySize,
                             SMEM_TOTAL);
        smem_set = 1;
    }

    prep_kernel<<<dim3(K_DIM / 64, 136), 256>>>(x);
    scatter_kernel<<<(nnz + 255) / 256, 256>>>(rows, cols, vals, nnz);
    gemm_kernel<<<dim3(M_DIM / BM, N_DIM / BN), THREADS, SMEM_TOTAL>>>(out);
}